// round 12
// baseline (speedup 1.0000x reference)
#include <cuda_runtime.h>
#include <cuda_fp16.h>
#include <cstdint>

// ---------------------------------------------------------------------------
// Problem constants
// ---------------------------------------------------------------------------
constexpr int B_ = 8;
constexpr int C_ = 1024;     // M and K of both GEMMs
constexpr int T_ = 2048;     // N of both GEMMs
constexpr long NELEM = (long)B_ * C_ * T_;   // 16,777,216

// d_out layout: [ret | tap | ff1 | ff2], each NELEM floats.

// ---------------------------------------------------------------------------
// Scratch (device globals)
// ---------------------------------------------------------------------------
__device__ __half g_xa[(size_t)B_ * C_ * T_];   // fp16(tap) : shared B operand
__device__ __half g_w1[(size_t)C_ * C_];
__device__ __half g_w2[(size_t)C_ * C_];
__device__ __half g_w12[(size_t)C_ * C_];       // fp16(W2 @ W1)
__device__ float  g_b12[C_];                    // W2 @ b1 + b2

// ---------------------------------------------------------------------------
// helpers
// ---------------------------------------------------------------------------
__device__ __forceinline__ uint32_t smem_u32(const void* p) {
    uint32_t a;
    asm("{ .reg .u64 t; cvta.to.shared.u64 t, %1; cvt.u32.u64 %0, t; }"
        : "=r"(a) : "l"(p));
    return a;
}
__device__ __forceinline__ void cp_async16(uint32_t sdst, const void* gsrc) {
    asm volatile("cp.async.cg.shared.global [%0], [%1], 16;" :: "r"(sdst), "l"(gsrc));
}
__device__ __forceinline__ void cp_commit() {
    asm volatile("cp.async.commit_group;" ::: "memory");
}
template <int N>
__device__ __forceinline__ void cp_wait() {
    asm volatile("cp.async.wait_group %0;" :: "n"(N) : "memory");
}
__device__ __forceinline__ void ldsm_x4(uint32_t (&r)[4], uint32_t addr) {
    asm volatile("ldmatrix.sync.aligned.m8n8.x4.shared.b16 {%0,%1,%2,%3}, [%4];"
        : "=r"(r[0]), "=r"(r[1]), "=r"(r[2]), "=r"(r[3]) : "r"(addr));
}
__device__ __forceinline__ void ldsm_x4t(uint32_t (&r)[4], uint32_t addr) {
    asm volatile("ldmatrix.sync.aligned.m8n8.x4.trans.shared.b16 {%0,%1,%2,%3}, [%4];"
        : "=r"(r[0]), "=r"(r[1]), "=r"(r[2]), "=r"(r[3]) : "r"(addr));
}
__device__ __forceinline__ void mma_f16(float (&d)[4],
                                        const uint32_t (&a)[4],
                                        const uint32_t* b) {
    asm volatile(
        "mma.sync.aligned.m16n8k16.row.col.f32.f16.f16.f32 "
        "{%0,%1,%2,%3}, {%4,%5,%6,%7}, {%8,%9}, {%0,%1,%2,%3};"
        : "+f"(d[0]), "+f"(d[1]), "+f"(d[2]), "+f"(d[3])
        : "r"(a[0]), "r"(a[1]), "r"(a[2]), "r"(a[3]), "r"(b[0]), "r"(b[1]));
}

// ---------------------------------------------------------------------------
// Kernel: W1, W2 -> fp16 (vectorized)
// ---------------------------------------------------------------------------
__global__ void wconv_kernel(const float* __restrict__ W1,
                             const float* __restrict__ W2)
{
    int i = blockIdx.x * 256 + threadIdx.x;     // float4 index
    float4 v1 = reinterpret_cast<const float4*>(W1)[i];
    float4 v2 = reinterpret_cast<const float4*>(W2)[i];
    __half2 a, b;
    a.x = __float2half(v1.x); a.y = __float2half(v1.y);
    b.x = __float2half(v1.z); b.y = __float2half(v1.w);
    reinterpret_cast<__half2*>(g_w1)[i * 2]     = a;
    reinterpret_cast<__half2*>(g_w1)[i * 2 + 1] = b;
    a.x = __float2half(v2.x); a.y = __float2half(v2.y);
    b.x = __float2half(v2.z); b.y = __float2half(v2.w);
    reinterpret_cast<__half2*>(g_w2)[i * 2]     = a;
    reinterpret_cast<__half2*>(g_w2)[i * 2 + 1] = b;
}

// ---------------------------------------------------------------------------
// Kernel: b12 = W2 @ b1 + b2
// ---------------------------------------------------------------------------
__global__ void bias12_kernel(const float* __restrict__ W2,
                              const float* __restrict__ b1,
                              const float* __restrict__ b2)
{
    int row = blockIdx.x * 8 + (threadIdx.x >> 5);
    int lane = threadIdx.x & 31;
    const float* wr = W2 + (size_t)row * C_;
    float s = 0.0f;
    #pragma unroll 8
    for (int j = lane; j < C_; j += 32) s += wr[j] * b1[j];
    #pragma unroll
    for (int o = 16; o; o >>= 1) s += __shfl_xor_sync(0xFFFFFFFFu, s, o);
    if (lane == 0) g_b12[row] = s + b2[row];
}

// ---------------------------------------------------------------------------
// Kernel: 4:1 mean pool -> tap (fp32) + fp16 copy into g_xa
// ---------------------------------------------------------------------------
__global__ void pool_kernel(const float* __restrict__ x, float* __restrict__ tap)
{
    long i0 = ((long)blockIdx.x * 256 + threadIdx.x) * 2;
    float4 v0 = reinterpret_cast<const float4*>(x)[i0];
    float4 v1 = reinterpret_cast<const float4*>(x)[i0 + 1];
    float m0 = 0.25f * (v0.x + v0.y + v0.z + v0.w);
    float m1 = 0.25f * (v1.x + v1.y + v1.z + v1.w);
    *reinterpret_cast<float2*>(tap + i0) = make_float2(m0, m1);
    __half2 h; h.x = __float2half(m0); h.y = __float2half(m1);
    *reinterpret_cast<__half2*>(g_xa + i0) = h;
}

// ---------------------------------------------------------------------------
// W12 GEMM: W12 = fp16(W2 @ W1)
// ---------------------------------------------------------------------------
constexpr int W_KC   = 64;
constexpr int W_ASTR = 144;
constexpr int W_BSTR = 272;
constexpr int W_OFB  = 64 * W_ASTR;               // 9216
constexpr int W_STAGE = W_OFB + W_KC * W_BSTR;    // 26624
constexpr int W_STAGES = 3;
constexpr int W_SMEM = W_STAGES * W_STAGE;        // 79872

__global__ __launch_bounds__(256, 1)
void w12_kernel()
{
    extern __shared__ __align__(128) char smem[];
    const uint32_t sb = smem_u32(smem);
    const int tid  = threadIdx.x;
    const int wid  = tid >> 5;
    const int lane = tid & 31;
    const int bn = blockIdx.x * 128;
    const int bm = blockIdx.y * 64;

    const int wm = (wid & 1) * 32;
    const int wn = (wid >> 1) * 32;

    auto load_stage = [&](int ch, int stg) {
        const int k0 = ch * W_KC;
        const uint32_t st = sb + stg * W_STAGE;
        #pragma unroll
        for (int i = 0; i < 2; i++) {
            int idx = tid + i * 256;
            int r = idx >> 3, c = idx & 7;
            cp_async16(st + r * W_ASTR + c * 16,
                       g_w2 + (size_t)(bm + r) * C_ + k0 + c * 8);
        }
        #pragma unroll
        for (int i = 0; i < 4; i++) {
            int idx = tid + i * 256;
            int r = idx >> 4, c = idx & 15;
            cp_async16(st + W_OFB + r * W_BSTR + c * 16,
                       g_w1 + (size_t)(k0 + r) * C_ + bn + c * 8);
        }
        cp_commit();
    };

    float acc[2][4][4];
    #pragma unroll
    for (int i = 0; i < 2; i++)
        #pragma unroll
        for (int j = 0; j < 4; j++)
            #pragma unroll
            for (int k = 0; k < 4; k++)
                acc[i][j][k] = 0.0f;

    load_stage(0, 0);
    load_stage(1, 1);

    const int lA_row = lane & 15;
    const int lA_kb  = (lane >> 4) * 16;
    const int lB_row = lane & 15;
    const int lB_nc  = (lane >> 4) * 8;

    for (int ch = 0; ch < C_ / W_KC; ch++) {
        cp_wait<W_STAGES - 2>();
        __syncthreads();
        if (ch + W_STAGES - 1 < C_ / W_KC)
            load_stage(ch + W_STAGES - 1, (ch + W_STAGES - 1) % W_STAGES);
        else
            cp_commit();
        const uint32_t st = sb + (ch % W_STAGES) * W_STAGE;

        #pragma unroll
        for (int ks = 0; ks < 4; ks++) {
            uint32_t b[4][2];
            #pragma unroll
            for (int nq = 0; nq < 2; nq++) {
                uint32_t r[4];
                uint32_t off = (uint32_t)((ks * 16 + lB_row) * W_BSTR
                                          + (wn + nq * 16 + lB_nc) * 2);
                ldsm_x4t(r, st + W_OFB + off);
                b[nq * 2 + 0][0] = r[0]; b[nq * 2 + 0][1] = r[1];
                b[nq * 2 + 1][0] = r[2]; b[nq * 2 + 1][1] = r[3];
            }
            #pragma unroll
            for (int mb = 0; mb < 2; mb++) {
                uint32_t a4[4];
                uint32_t off = (uint32_t)((wm + mb * 16 + lA_row) * W_ASTR
                                          + ks * 32 + lA_kb);
                ldsm_x4(a4, st + off);
                #pragma unroll
                for (int nb = 0; nb < 4; nb++)
                    mma_f16(acc[mb][nb], a4, b[nb]);
            }
        }
    }

    const int r_lo = lane >> 2;
    const int c_lo = (lane & 3) * 2;
    #pragma unroll
    for (int mb = 0; mb < 2; mb++) {
        int gr0 = bm + wm + mb * 16 + r_lo;
        int gr1 = gr0 + 8;
        #pragma unroll
        for (int nb = 0; nb < 4; nb++) {
            int col = bn + wn + nb * 8 + c_lo;
            __half2 h0; h0.x = __float2half(acc[mb][nb][0]);
                        h0.y = __float2half(acc[mb][nb][1]);
            __half2 h1; h1.x = __float2half(acc[mb][nb][2]);
                        h1.y = __float2half(acc[mb][nb][3]);
            *reinterpret_cast<__half2*>(g_w12 + (size_t)gr0 * C_ + col) = h0;
            *reinterpret_cast<__half2*>(g_w12 + (size_t)gr1 * C_ + col) = h1;
        }
    }
}

// ---------------------------------------------------------------------------
// Merged GEMM + fused window epilogue:
//   z <  8 : ff1 = W1  @ xa + b1   (batch z)
//   z >= 8 : ff2 = W12 @ xa + b12  (batch z-8), then compute ret for all
//            window positions fully inside this CTA's 256-col tile.
// ---------------------------------------------------------------------------
constexpr int KC = 32;
constexpr int A_STR = 80;
constexpr int B_STR = 528;
constexpr int OF_A = 0;
constexpr int OF_B = 128 * A_STR;
constexpr int STAGE_BYTES = OF_B + KC * B_STR;    // 27136
constexpr int STAGES = 4;
constexpr int GEMM_SMEM = STAGES * STAGE_BYTES;   // 108544
constexpr int NCHUNK = C_ / KC;                   // 32
constexpr int RS = 260;                           // staged row stride (floats)
constexpr int PRE_OFF = 64 * RS * 4;              // 66560 bytes; pre[64][68] after

__global__ __launch_bounds__(512, 1)
void gemm_kernel(const float* __restrict__ b1,
                 float* __restrict__ ff1,
                 float* __restrict__ ff2,
                 float* __restrict__ ret)
{
    extern __shared__ __align__(128) char smem[];
    const uint32_t sb = smem_u32(smem);

    const int tid  = threadIdx.x;
    const int wid  = tid >> 5;
    const int lane = tid & 31;
    const int bn = blockIdx.x * 256;
    const int bm = blockIdx.y * 128;
    const int bz = blockIdx.z;
    const int batch = bz & 7;
    const bool second = bz >= 8;

    const __half* W    = second ? g_w12 : g_w1;
    const float*  bias = second ? g_b12 : b1;
    float* out = (second ? ff2 : ff1) + (size_t)batch * C_ * T_;
    const __half* Xb = g_xa + (size_t)batch * C_ * T_;

    const int wm = (wid & 3) * 32;
    const int wn = (wid >> 2) * 64;

    const int a_r = tid >> 2;
    const int a_c = tid & 3;
    const int b_k = tid >> 5;
    const int b_c = tid & 31;

    auto load_stage = [&](int ch, int stg) {
        const int k0 = ch * KC;
        const uint32_t st = sb + stg * STAGE_BYTES;
        cp_async16(st + OF_A + a_r * A_STR + a_c * 16,
                   W + (size_t)(bm + a_r) * C_ + k0 + a_c * 8);
        #pragma unroll
        for (int i = 0; i < 2; i++) {
            int kr = b_k + i * 16;
            cp_async16(st + OF_B + kr * B_STR + b_c * 16,
                       Xb + (size_t)(k0 + kr) * T_ + bn + b_c * 8);
        }
        cp_commit();
    };

    float acc[2][8][4];
    #pragma unroll
    for (int i = 0; i < 2; i++)
        #pragma unroll
        for (int j = 0; j < 8; j++)
            #pragma unroll
            for (int k = 0; k < 4; k++)
                acc[i][j][k] = 0.0f;

    load_stage(0, 0);
    load_stage(1, 1);
    load_stage(2, 2);

    const int lA_row = lane & 15;
    const int lA_kb  = (lane >> 4) * 16;
    const int lB_row = lane & 15;
    const int lB_nc  = (lane >> 4) * 8;

    for (int ch = 0; ch < NCHUNK; ch++) {
        cp_wait<STAGES - 2>();
        __syncthreads();

        if (ch + STAGES - 1 < NCHUNK)
            load_stage(ch + STAGES - 1, (ch + STAGES - 1) % STAGES);
        else
            cp_commit();

        const uint32_t st = sb + (ch % STAGES) * STAGE_BYTES;

        #pragma unroll
        for (int ks = 0; ks < 2; ks++) {
            uint32_t b[8][2];
            #pragma unroll
            for (int nq = 0; nq < 4; nq++) {
                uint32_t r[4];
                uint32_t off = (uint32_t)((ks * 16 + lB_row) * B_STR
                                          + (wn + nq * 16 + lB_nc) * 2);
                ldsm_x4t(r, st + OF_B + off);
                b[nq * 2 + 0][0] = r[0]; b[nq * 2 + 0][1] = r[1];
                b[nq * 2 + 1][0] = r[2]; b[nq * 2 + 1][1] = r[3];
            }
            #pragma unroll
            for (int mb = 0; mb < 2; mb++) {
                uint32_t a4[4];
                uint32_t offA = (uint32_t)((wm + mb * 16 + lA_row) * A_STR
                                           + ks * 32 + lA_kb);
                ldsm_x4(a4, st + OF_A + offA);
                #pragma unroll
                for (int nb = 0; nb < 8; nb++)
                    mma_f16(acc[mb][nb], a4, b[nb]);
            }
        }
    }

    // ---- standard epilogue: bias + fp32 store ----
    const int r_lo = lane >> 2;
    const int c_lo = (lane & 3) * 2;
    #pragma unroll
    for (int mb = 0; mb < 2; mb++) {
        int gr0 = bm + wm + mb * 16 + r_lo;
        int gr1 = gr0 + 8;
        float bv0 = bias[gr0];
        float bv1 = bias[gr1];
        size_t ro0 = (size_t)gr0 * T_ + bn + wn + c_lo;
        size_t ro1 = (size_t)gr1 * T_ + bn + wn + c_lo;
        #pragma unroll
        for (int nb = 0; nb < 8; nb++) {
            *reinterpret_cast<float2*>(out + ro0 + nb * 8) =
                make_float2(acc[mb][nb][0] + bv0, acc[mb][nb][1] + bv0);
            *reinterpret_cast<float2*>(out + ro1 + nb * 8) =
                make_float2(acc[mb][nb][2] + bv1, acc[mb][nb][3] + bv1);
        }
    }

    // ---- fused window (ff2 CTAs only) ----
    if (second) {
        float* retb = ret + (size_t)batch * C_ * T_;
        float* srow = reinterpret_cast<float*>(smem);            // [64][RS]
        float* spre = reinterpret_cast<float*>(smem + PRE_OFF);  // [64][68]
        #pragma unroll
        for (int ph = 0; ph < 2; ph++) {
            __syncthreads();   // ph0: also fences last-chunk ldsm reads
            if (((wid & 3) >> 1) == ph) {
                #pragma unroll
                for (int mb = 0; mb < 2; mb++) {
                    int gr = wm + mb * 16 + r_lo;
                    int r0 = gr - 64 * ph;                // 0..55
                    float bv0 = bias[bm + gr];
                    float bv1 = bias[bm + gr + 8];
                    #pragma unroll
                    for (int nb = 0; nb < 8; nb++) {
                        int col = wn + nb * 8 + c_lo;
                        *reinterpret_cast<float2*>(&srow[r0 * RS + col]) =
                            make_float2(acc[mb][nb][0] + bv0, acc[mb][nb][1] + bv0);
                        *reinterpret_cast<float2*>(&srow[(r0 + 8) * RS + col]) =
                            make_float2(acc[mb][nb][2] + bv1, acc[mb][nb][3] + bv1);
                    }
                }
            }
            __syncthreads();
            // per-group (4-col) partial sums
            #pragma unroll
            for (int i = 0; i < 8; i++) {
                int idx = tid + i * 512;
                int rl = idx >> 6, q = idx & 63;
                float4 v = *reinterpret_cast<float4*>(&srow[rl * RS + q * 4]);
                spre[rl * 68 + q] = v.x + v.y + v.z + v.w;
            }
            __syncthreads();
            // window outputs for gl >= 4 (L = 16 exact)
            #pragma unroll
            for (int i = 0; i < 8; i++) {
                int idx = tid + i * 512;
                int rl = idx >> 6, gl = idx & 63;
                if (gl >= 4) {
                    float sum = srow[rl * RS + 4 * gl] - srow[rl * RS + 4 * gl - 16]
                              + spre[rl * 68 + gl - 4] + spre[rl * 68 + gl - 3]
                              + spre[rl * 68 + gl - 2] + spre[rl * 68 + gl - 1];
                    float avg = sum * 0.0625f;
                    *reinterpret_cast<float4*>(
                        retb + (size_t)(bm + 64 * ph + rl) * T_ + bn + 4 * gl)
                        = make_float4(avg, avg, avg, avg);
                }
            }
        }
    }
}

// ---------------------------------------------------------------------------
// Fixup: window outputs whose window crosses a 256-col tile boundary
// (gl in [0,4) of each chunk), incl. the L<16 head cases. One warp per row,
// one lane per deferred g.
// ---------------------------------------------------------------------------
__global__ void fixup_kernel(const float* __restrict__ ff2, float* __restrict__ ret)
{
    int row = blockIdx.x * 8 + (threadIdx.x >> 5);   // B*C = 8192 rows
    int lane = threadIdx.x & 31;
    int c = lane >> 2, j = lane & 3;                 // chunk 0..7, pos 0..3
    int g = c * 64 + j;
    int L = min(4 * g + 1, 16);
    const float* p = ff2 + (size_t)row * T_;
    float sum = 0.0f;
    for (int t = 4 * g - L + 1; t <= 4 * g; t++) sum += p[t];
    float avg = sum / (float)L;
    *reinterpret_cast<float4*>(ret + (size_t)row * T_ + 4 * g) =
        make_float4(avg, avg, avg, avg);
}

// ---------------------------------------------------------------------------
// Launcher — weights path forked onto a side stream, overlapping pool.
// ---------------------------------------------------------------------------
extern "C" void kernel_launch(void* const* d_in, const int* in_sizes, int n_in,
                              void* d_out, int out_size)
{
    const float* x  = (const float*)d_in[0];
    const float* W1 = (const float*)d_in[1];
    const float* b1 = (const float*)d_in[2];
    const float* W2 = (const float*)d_in[3];
    const float* b2 = (const float*)d_in[4];

    float* out = (float*)d_out;
    float* ret = out;
    float* tap = out + NELEM;
    float* ff1 = out + 2 * NELEM;
    float* ff2 = out + 3 * NELEM;

    static cudaStream_t s1 = nullptr;
    static cudaEvent_t evFork = nullptr, evJoin = nullptr;
    if (!s1) {
        cudaStreamCreateWithFlags(&s1, cudaStreamNonBlocking);
        cudaEventCreateWithFlags(&evFork, cudaEventDisableTiming);
        cudaEventCreateWithFlags(&evJoin, cudaEventDisableTiming);
        cudaFuncSetAttribute(gemm_kernel,
                             cudaFuncAttributeMaxDynamicSharedMemorySize, GEMM_SMEM);
        cudaFuncSetAttribute(w12_kernel,
                             cudaFuncAttributeMaxDynamicSharedMemorySize, W_SMEM);
    }

    // fork: weights path on s1
    cudaEventRecord(evFork, 0);
    cudaStreamWaitEvent(s1, evFork, 0);

    wconv_kernel<<<(C_ * C_) / 1024, 256, 0, s1>>>(W1, W2);
    {
        dim3 grid(C_ / 128, C_ / 64);
        w12_kernel<<<grid, 256, W_SMEM, s1>>>();
    }
    bias12_kernel<<<C_ / 8, 256, 0, s1>>>(W2, b1, b2);
    cudaEventRecord(evJoin, s1);

    // main stream: pool (overlaps weights path)
    pool_kernel<<<(int)(NELEM / 512), 256>>>(x, tap);

    // join before merged GEMM
    cudaStreamWaitEvent(0, evJoin, 0);

    // merged GEMM (ff1 + ff2) with fused window epilogue
    {
        dim3 grid(T_ / 256, C_ / 128, 2 * B_);
        gemm_kernel<<<grid, 512, GEMM_SMEM>>>(b1, ff1, ff2, ret);
    }

    // boundary window outputs
    fixup_kernel<<<(B_ * C_) / 8, 256>>>(ff2, ret);
}

// round 14
// speedup vs baseline: 1.0045x; 1.0045x over previous
#include <cuda_runtime.h>
#include <cuda_fp16.h>
#include <cstdint>

// ---------------------------------------------------------------------------
// Problem constants
// ---------------------------------------------------------------------------
constexpr int B_ = 8;
constexpr int C_ = 1024;     // M and K of both GEMMs
constexpr int T_ = 2048;     // N of both GEMMs
constexpr long NELEM = (long)B_ * C_ * T_;   // 16,777,216
constexpr long CT   = (long)C_ * T_;         // per-batch elements
constexpr int HB   = B_ / 2;                 // batches per half

// d_out layout: [ret | tap | ff1 | ff2], each NELEM floats.

// ---------------------------------------------------------------------------
// Scratch (device globals)
// ---------------------------------------------------------------------------
__device__ __half g_xa[(size_t)B_ * C_ * T_];   // fp16(tap) : shared B operand
__device__ __half g_w1[(size_t)C_ * C_];
__device__ __half g_w2[(size_t)C_ * C_];
__device__ __half g_w12[(size_t)C_ * C_];       // fp16(W2 @ W1)
__device__ float  g_b12[C_];                    // W2 @ b1 + b2

// ---------------------------------------------------------------------------
// helpers
// ---------------------------------------------------------------------------
__device__ __forceinline__ uint32_t smem_u32(const void* p) {
    uint32_t a;
    asm("{ .reg .u64 t; cvta.to.shared.u64 t, %1; cvt.u32.u64 %0, t; }"
        : "=r"(a) : "l"(p));
    return a;
}
__device__ __forceinline__ void cp_async16(uint32_t sdst, const void* gsrc) {
    asm volatile("cp.async.cg.shared.global [%0], [%1], 16;" :: "r"(sdst), "l"(gsrc));
}
__device__ __forceinline__ void cp_commit() {
    asm volatile("cp.async.commit_group;" ::: "memory");
}
template <int N>
__device__ __forceinline__ void cp_wait() {
    asm volatile("cp.async.wait_group %0;" :: "n"(N) : "memory");
}
__device__ __forceinline__ void ldsm_x4(uint32_t (&r)[4], uint32_t addr) {
    asm volatile("ldmatrix.sync.aligned.m8n8.x4.shared.b16 {%0,%1,%2,%3}, [%4];"
        : "=r"(r[0]), "=r"(r[1]), "=r"(r[2]), "=r"(r[3]) : "r"(addr));
}
__device__ __forceinline__ void ldsm_x4t(uint32_t (&r)[4], uint32_t addr) {
    asm volatile("ldmatrix.sync.aligned.m8n8.x4.trans.shared.b16 {%0,%1,%2,%3}, [%4];"
        : "=r"(r[0]), "=r"(r[1]), "=r"(r[2]), "=r"(r[3]) : "r"(addr));
}
__device__ __forceinline__ void mma_f16(float (&d)[4],
                                        const uint32_t (&a)[4],
                                        const uint32_t* b) {
    asm volatile(
        "mma.sync.aligned.m16n8k16.row.col.f32.f16.f16.f32 "
        "{%0,%1,%2,%3}, {%4,%5,%6,%7}, {%8,%9}, {%0,%1,%2,%3};"
        : "+f"(d[0]), "+f"(d[1]), "+f"(d[2]), "+f"(d[3])
        : "r"(a[0]), "r"(a[1]), "r"(a[2]), "r"(a[3]), "r"(b[0]), "r"(b[1]));
}

// ---------------------------------------------------------------------------
// Kernel: W1, W2 -> fp16 (vectorized)
// ---------------------------------------------------------------------------
__global__ void wconv_kernel(const float* __restrict__ W1,
                             const float* __restrict__ W2)
{
    int i = blockIdx.x * 256 + threadIdx.x;     // float4 index
    float4 v1 = reinterpret_cast<const float4*>(W1)[i];
    float4 v2 = reinterpret_cast<const float4*>(W2)[i];
    __half2 a, b;
    a.x = __float2half(v1.x); a.y = __float2half(v1.y);
    b.x = __float2half(v1.z); b.y = __float2half(v1.w);
    reinterpret_cast<__half2*>(g_w1)[i * 2]     = a;
    reinterpret_cast<__half2*>(g_w1)[i * 2 + 1] = b;
    a.x = __float2half(v2.x); a.y = __float2half(v2.y);
    b.x = __float2half(v2.z); b.y = __float2half(v2.w);
    reinterpret_cast<__half2*>(g_w2)[i * 2]     = a;
    reinterpret_cast<__half2*>(g_w2)[i * 2 + 1] = b;
}

// ---------------------------------------------------------------------------
// Kernel: b12 = W2 @ b1 + b2
// ---------------------------------------------------------------------------
__global__ void bias12_kernel(const float* __restrict__ W2,
                              const float* __restrict__ b1,
                              const float* __restrict__ b2)
{
    int row = blockIdx.x * 8 + (threadIdx.x >> 5);
    int lane = threadIdx.x & 31;
    const float* wr = W2 + (size_t)row * C_;
    float s = 0.0f;
    #pragma unroll 8
    for (int j = lane; j < C_; j += 32) s += wr[j] * b1[j];
    #pragma unroll
    for (int o = 16; o; o >>= 1) s += __shfl_xor_sync(0xFFFFFFFFu, s, o);
    if (lane == 0) g_b12[row] = s + b2[row];
}

// ---------------------------------------------------------------------------
// Kernel: half-batch 4:1 mean pool -> tap (fp32) + fp16 into xa
// ---------------------------------------------------------------------------
__global__ void pool_kernel(const float4* __restrict__ x4,
                            float* __restrict__ tap,
                            __half* __restrict__ xa)
{
    long i0 = ((long)blockIdx.x * 256 + threadIdx.x) * 2;
    float4 v0 = x4[i0];
    float4 v1 = x4[i0 + 1];
    float m0 = 0.25f * (v0.x + v0.y + v0.z + v0.w);
    float m1 = 0.25f * (v1.x + v1.y + v1.z + v1.w);
    *reinterpret_cast<float2*>(tap + i0) = make_float2(m0, m1);
    __half2 h; h.x = __float2half(m0); h.y = __float2half(m1);
    *reinterpret_cast<__half2*>(xa + i0) = h;
}

// ---------------------------------------------------------------------------
// W12 GEMM: W12 = fp16(W2 @ W1)
// ---------------------------------------------------------------------------
constexpr int W_KC   = 64;
constexpr int W_ASTR = 144;
constexpr int W_BSTR = 272;
constexpr int W_OFB  = 64 * W_ASTR;               // 9216
constexpr int W_STAGE = W_OFB + W_KC * W_BSTR;    // 26624
constexpr int W_STAGES = 3;
constexpr int W_SMEM = W_STAGES * W_STAGE;        // 79872

__global__ __launch_bounds__(256, 1)
void w12_kernel()
{
    extern __shared__ __align__(128) char smem[];
    const uint32_t sb = smem_u32(smem);
    const int tid  = threadIdx.x;
    const int wid  = tid >> 5;
    const int lane = tid & 31;
    const int bn = blockIdx.x * 128;
    const int bm = blockIdx.y * 64;

    const int wm = (wid & 1) * 32;
    const int wn = (wid >> 1) * 32;

    auto load_stage = [&](int ch, int stg) {
        const int k0 = ch * W_KC;
        const uint32_t st = sb + stg * W_STAGE;
        #pragma unroll
        for (int i = 0; i < 2; i++) {
            int idx = tid + i * 256;
            int r = idx >> 3, c = idx & 7;
            cp_async16(st + r * W_ASTR + c * 16,
                       g_w2 + (size_t)(bm + r) * C_ + k0 + c * 8);
        }
        #pragma unroll
        for (int i = 0; i < 4; i++) {
            int idx = tid + i * 256;
            int r = idx >> 4, c = idx & 15;
            cp_async16(st + W_OFB + r * W_BSTR + c * 16,
                       g_w1 + (size_t)(k0 + r) * C_ + bn + c * 8);
        }
        cp_commit();
    };

    float acc[2][4][4];
    #pragma unroll
    for (int i = 0; i < 2; i++)
        #pragma unroll
        for (int j = 0; j < 4; j++)
            #pragma unroll
            for (int k = 0; k < 4; k++)
                acc[i][j][k] = 0.0f;

    load_stage(0, 0);
    load_stage(1, 1);

    const int lA_row = lane & 15;
    const int lA_kb  = (lane >> 4) * 16;
    const int lB_row = lane & 15;
    const int lB_nc  = (lane >> 4) * 8;

    for (int ch = 0; ch < C_ / W_KC; ch++) {
        cp_wait<W_STAGES - 2>();
        __syncthreads();
        if (ch + W_STAGES - 1 < C_ / W_KC)
            load_stage(ch + W_STAGES - 1, (ch + W_STAGES - 1) % W_STAGES);
        else
            cp_commit();
        const uint32_t st = sb + (ch % W_STAGES) * W_STAGE;

        #pragma unroll
        for (int ks = 0; ks < 4; ks++) {
            uint32_t b[4][2];
            #pragma unroll
            for (int nq = 0; nq < 2; nq++) {
                uint32_t r[4];
                uint32_t off = (uint32_t)((ks * 16 + lB_row) * W_BSTR
                                          + (wn + nq * 16 + lB_nc) * 2);
                ldsm_x4t(r, st + W_OFB + off);
                b[nq * 2 + 0][0] = r[0]; b[nq * 2 + 0][1] = r[1];
                b[nq * 2 + 1][0] = r[2]; b[nq * 2 + 1][1] = r[3];
            }
            #pragma unroll
            for (int mb = 0; mb < 2; mb++) {
                uint32_t a4[4];
                uint32_t off = (uint32_t)((wm + mb * 16 + lA_row) * W_ASTR
                                          + ks * 32 + lA_kb);
                ldsm_x4(a4, st + off);
                #pragma unroll
                for (int nb = 0; nb < 4; nb++)
                    mma_f16(acc[mb][nb], a4, b[nb]);
            }
        }
    }

    const int r_lo = lane >> 2;
    const int c_lo = (lane & 3) * 2;
    #pragma unroll
    for (int mb = 0; mb < 2; mb++) {
        int gr0 = bm + wm + mb * 16 + r_lo;
        int gr1 = gr0 + 8;
        #pragma unroll
        for (int nb = 0; nb < 4; nb++) {
            int col = bn + wn + nb * 8 + c_lo;
            __half2 h0; h0.x = __float2half(acc[mb][nb][0]);
                        h0.y = __float2half(acc[mb][nb][1]);
            __half2 h1; h1.x = __float2half(acc[mb][nb][2]);
                        h1.y = __float2half(acc[mb][nb][3]);
            *reinterpret_cast<__half2*>(g_w12 + (size_t)gr0 * C_ + col) = h0;
            *reinterpret_cast<__half2*>(g_w12 + (size_t)gr1 * C_ + col) = h1;
        }
    }
}

// ---------------------------------------------------------------------------
// Half-batch GEMM: grid (T/256, C/128, 2*HB). z: batch = z>>1, z&1 selects
//   0: ff1_b = W1  @ xa_b + b1
//   1: ff2_b = W12 @ xa_b + b12
// CTA tile 128x256, KC=32, 4-stage cp.async, 256 threads, warp tile 64x64.
// ---------------------------------------------------------------------------
constexpr int KC = 32;
constexpr int A_STR = 80;
constexpr int B_STR = 528;
constexpr int OF_A = 0;
constexpr int OF_B = 128 * A_STR;                 // 10240
constexpr int STAGE_BYTES = OF_B + KC * B_STR;    // 27136
constexpr int STAGES = 4;
constexpr int GEMM_SMEM = STAGES * STAGE_BYTES;   // 108544
constexpr int NCHUNK = C_ / KC;                   // 32

__global__ __launch_bounds__(256, 1)
void gemm_kernel(const float* __restrict__ b1,
                 const __half* __restrict__ xa_h,   // half-batch base
                 float* __restrict__ ff1_h,
                 float* __restrict__ ff2_h)
{
    extern __shared__ __align__(128) char smem[];
    const uint32_t sb = smem_u32(smem);

    const int tid  = threadIdx.x;
    const int wid  = tid >> 5;
    const int lane = tid & 31;
    const int bn = blockIdx.x * 256;
    const int bm = blockIdx.y * 128;
    const int batch = blockIdx.z >> 1;
    const bool second = (blockIdx.z & 1);

    const __half* W    = second ? g_w12 : g_w1;
    const float*  bias = second ? g_b12 : b1;
    float* out = (second ? ff2_h : ff1_h) + (size_t)batch * CT;
    const __half* Xb = xa_h + (size_t)batch * CT;

    const int wm = (wid & 1) * 64;     // 2 warps over M
    const int wn = (wid >> 1) * 64;    // 4 warps over N

    const int a_r = tid >> 2;
    const int a_c = tid & 3;
    const int b_k = tid >> 5;
    const int b_c = tid & 31;

    auto load_stage = [&](int ch, int stg) {
        const int k0 = ch * KC;
        const uint32_t st = sb + stg * STAGE_BYTES;
        #pragma unroll
        for (int i = 0; i < 2; i++) {
            int r = a_r + i * 64;
            cp_async16(st + OF_A + r * A_STR + a_c * 16,
                       W + (size_t)(bm + r) * C_ + k0 + a_c * 8);
        }
        #pragma unroll
        for (int i = 0; i < 4; i++) {
            int kr = b_k + i * 8;
            cp_async16(st + OF_B + kr * B_STR + b_c * 16,
                       Xb + (size_t)(k0 + kr) * T_ + bn + b_c * 8);
        }
        cp_commit();
    };

    float acc[4][8][4];
    #pragma unroll
    for (int i = 0; i < 4; i++)
        #pragma unroll
        for (int j = 0; j < 8; j++)
            #pragma unroll
            for (int k = 0; k < 4; k++)
                acc[i][j][k] = 0.0f;

    load_stage(0, 0);
    load_stage(1, 1);
    load_stage(2, 2);

    const int lA_row = lane & 15;
    const int lA_kb  = (lane >> 4) * 16;
    const int lB_row = lane & 15;
    const int lB_nc  = (lane >> 4) * 8;

    for (int ch = 0; ch < NCHUNK; ch++) {
        cp_wait<STAGES - 2>();
        __syncthreads();

        if (ch + STAGES - 1 < NCHUNK)
            load_stage(ch + STAGES - 1, (ch + STAGES - 1) % STAGES);
        else
            cp_commit();

        const uint32_t st = sb + (ch % STAGES) * STAGE_BYTES;

        #pragma unroll
        for (int ks = 0; ks < 2; ks++) {
            uint32_t b[8][2];
            #pragma unroll
            for (int nq = 0; nq < 4; nq++) {
                uint32_t r[4];
                uint32_t off = (uint32_t)((ks * 16 + lB_row) * B_STR
                                          + (wn + nq * 16 + lB_nc) * 2);
                ldsm_x4t(r, st + OF_B + off);
                b[nq * 2 + 0][0] = r[0]; b[nq * 2 + 0][1] = r[1];
                b[nq * 2 + 1][0] = r[2]; b[nq * 2 + 1][1] = r[3];
            }
            #pragma unroll
            for (int mb = 0; mb < 4; mb++) {
                uint32_t a4[4];
                uint32_t offA = (uint32_t)((wm + mb * 16 + lA_row) * A_STR
                                           + ks * 32 + lA_kb);
                ldsm_x4(a4, st + OF_A + offA);
                #pragma unroll
                for (int nb = 0; nb < 8; nb++)
                    mma_f16(acc[mb][nb], a4, b[nb]);
            }
        }
    }

    // epilogue: bias + fp32 store
    const int r_lo = lane >> 2;
    const int c_lo = (lane & 3) * 2;
    #pragma unroll
    for (int mb = 0; mb < 4; mb++) {
        int gr0 = bm + wm + mb * 16 + r_lo;
        int gr1 = gr0 + 8;
        float bv0 = bias[gr0];
        float bv1 = bias[gr1];
        size_t ro0 = (size_t)gr0 * T_ + bn + wn + c_lo;
        size_t ro1 = (size_t)gr1 * T_ + bn + wn + c_lo;
        #pragma unroll
        for (int nb = 0; nb < 8; nb++) {
            *reinterpret_cast<float2*>(out + ro0 + nb * 8) =
                make_float2(acc[mb][nb][0] + bv0, acc[mb][nb][1] + bv0);
            *reinterpret_cast<float2*>(out + ro1 + nb * 8) =
                make_float2(acc[mb][nb][2] + bv1, acc[mb][nb][3] + bv1);
        }
    }
}

// ---------------------------------------------------------------------------
// Kernel: half-batch causal windowed mean via per-group partial sums.
// ---------------------------------------------------------------------------
__global__ void window_kernel(const float* __restrict__ ff2h,
                              float* __restrict__ reth)
{
    __shared__ float s[T_];
    __shared__ float pre[T_ / 4];
    const size_t row = blockIdx.x;
    const float4* p4 = reinterpret_cast<const float4*>(ff2h + row * T_);
    float4* s4 = reinterpret_cast<float4*>(s);
    #pragma unroll
    for (int i = 0; i < 2; i++) {
        int idx = threadIdx.x + i * 256;
        float4 v = p4[idx];
        s4[idx] = v;
        pre[idx] = v.x + v.y + v.z + v.w;
    }
    __syncthreads();
    float4* r4 = reinterpret_cast<float4*>(reth + row * T_);
    #pragma unroll
    for (int i = 0; i < 2; i++) {
        int g = threadIdx.x + i * 256;
        float avg;
        if (g >= 4) {
            float sum = s[4 * g] - s[4 * g - 16]
                      + pre[g - 4] + pre[g - 3] + pre[g - 2] + pre[g - 1];
            avg = sum * 0.0625f;
        } else {
            float sum = s[4 * g];
            for (int q = 0; q < g; q++) sum += pre[q];
            avg = sum / (float)(4 * g + 1);
        }
        r4[g] = make_float4(avg, avg, avg, avg);
    }
}

// ---------------------------------------------------------------------------
// Launcher — two-half pipeline, 2 streams, 5 events:
//   main: pool_h0, pool_h1, window_h0(evG0), window_h1(evG1)
//   s1:   wconv, w12, bias12, gemm_h0(evP0), gemm_h1(evP1)
// ---------------------------------------------------------------------------
extern "C" void kernel_launch(void* const* d_in, const int* in_sizes, int n_in,
                              void* d_out, int out_size)
{
    const float* x  = (const float*)d_in[0];
    const float* W1 = (const float*)d_in[1];
    const float* b1 = (const float*)d_in[2];
    const float* W2 = (const float*)d_in[3];
    const float* b2 = (const float*)d_in[4];

    float* out = (float*)d_out;
    float* ret = out;
    float* tap = out + NELEM;
    float* ff1 = out + 2 * NELEM;
    float* ff2 = out + 3 * NELEM;

    static cudaStream_t s1 = nullptr;
    static cudaEvent_t evFork, evP0, evP1, evG0, evG1;
    static __half* xa = nullptr;
    if (!s1) {
        cudaStreamCreateWithFlags(&s1, cudaStreamNonBlocking);
        cudaEventCreateWithFlags(&evFork, cudaEventDisableTiming);
        cudaEventCreateWithFlags(&evP0, cudaEventDisableTiming);
        cudaEventCreateWithFlags(&evP1, cudaEventDisableTiming);
        cudaEventCreateWithFlags(&evG0, cudaEventDisableTiming);
        cudaEventCreateWithFlags(&evG1, cudaEventDisableTiming);
        cudaGetSymbolAddress((void**)&xa, g_xa);
        cudaFuncSetAttribute(gemm_kernel,
                             cudaFuncAttributeMaxDynamicSharedMemorySize, GEMM_SMEM);
        cudaFuncSetAttribute(w12_kernel,
                             cudaFuncAttributeMaxDynamicSharedMemorySize, W_SMEM);
    }

    const long HCT = (long)HB * CT;   // elements per half

    // fork
    cudaEventRecord(evFork, 0);
    cudaStreamWaitEvent(s1, evFork, 0);

    // s1: weights path
    wconv_kernel<<<(C_ * C_) / 1024, 256, 0, s1>>>(W1, W2);
    {
        dim3 grid(C_ / 128, C_ / 64);
        w12_kernel<<<grid, 256, W_SMEM, s1>>>();
    }
    bias12_kernel<<<C_ / 8, 256, 0, s1>>>(W2, b1, b2);

    // main: pools (half 0, half 1)
    pool_kernel<<<(int)(HCT / 512), 256>>>(
        reinterpret_cast<const float4*>(x), tap, xa);
    cudaEventRecord(evP0, 0);
    pool_kernel<<<(int)(HCT / 512), 256>>>(
        reinterpret_cast<const float4*>(x) + HCT, tap + HCT, xa + HCT);
    cudaEventRecord(evP1, 0);

    // s1: gemm half 0, gemm half 1
    cudaStreamWaitEvent(s1, evP0, 0);
    {
        dim3 grid(T_ / 256, C_ / 128, 2 * HB);
        gemm_kernel<<<grid, 256, GEMM_SMEM, s1>>>(b1, xa, ff1, ff2);
    }
    cudaEventRecord(evG0, s1);
    cudaStreamWaitEvent(s1, evP1, 0);
    {
        dim3 grid(T_ / 256, C_ / 128, 2 * HB);
        gemm_kernel<<<grid, 256, GEMM_SMEM, s1>>>(b1, xa + HCT,
                                                  ff1 + HCT, ff2 + HCT);
    }
    cudaEventRecord(evG1, s1);

    // main: windows (half 0 overlaps gemm half 1)
    cudaStreamWaitEvent(0, evG0, 0);
    window_kernel<<<HB * C_, 256>>>(ff2, ret);
    cudaStreamWaitEvent(0, evG1, 0);
    window_kernel<<<HB * C_, 256>>>(ff2 + HCT, ret + HCT);
}